// round 13
// baseline (speedup 1.0000x reference)
#include <cuda_runtime.h>
#include <cuda_bf16.h>

// ---------------- problem constants ----------------
#define BATCH   4
#define NPTS    32768
#define NCLS    3
#define KSEL    4096          // NMS_PRE_MAXSIZE
#define KPOST   512           // NMS_POST_MAXSIZE
#define NWORDS  64            // 4096 / 64
#define NW1     16            // stage-0: first 1024 boxes
#define NBUCK   4096          // fine monotone buckets
#define CAND_CAP 6144         // smem candidate staging capacity
#define MSW     1088          // padded smem stride per mask word (64*17)

#define ROIS_ELEMS   (BATCH * KPOST * 7)          // 14336
#define SC_OFF       (ROIS_ELEMS)                 // 14336
#define LB_OFF       (ROIS_ELEMS + BATCH * KPOST) // 16384

// ---------------- device scratch (no allocations allowed) ----------------
__device__ int                g_hist[BATCH][NBUCK];         // self-zeroed by k_select
__device__ unsigned long long g_keyfull[BATCH][NPTS];       // 1 MB
__device__ unsigned long long g_cand[BATCH][NPTS];          // overflow path only
__device__ float4             g_box4[BATCH][KSEL];          // x1,y1,x2,y2
__device__ float              g_area[BATCH][KSEL];
__device__ float              g_rois[BATCH][KSEL][7];
__device__ float              g_scores[BATCH][KSEL];
__device__ unsigned char      g_labels[BATCH][KSEL];
__device__ unsigned long long g_mask0[BATCH][1024 * NW1];   // 512 KB [row][word16]
                                                            // lower-tri blocks stay 0

// ---------------- helpers ----------------
__device__ __forceinline__ unsigned f2ord(float s) {
    unsigned u = __float_as_uint(s);
    return (u & 0x80000000u) ? ~u : (u | 0x80000000u);
}

// monotone (non-decreasing in u) bucket; fine resolution for s>=0.5
__device__ __forceinline__ int bucket_of(unsigned u) {
    if (u >= 0xBF000000u) {
        unsigned f = 2048u + ((u - 0xBF000000u) >> 12);
        return (int)(f > 4095u ? 4095u : f);
    }
    return (int)(u >> 21);                           // <= 1528 < 2048, monotone
}

// exact-rounding IOU>thresh, identical op order to reference
__device__ __forceinline__ bool iou_gt(float4 A, float aA, float4 B, float aB) {
    float ix = __fsub_rn(fminf(A.z, B.z), fmaxf(A.x, B.x));
    float iy = __fsub_rn(fminf(A.w, B.w), fmaxf(A.y, B.y));
    if (ix > 0.0f && iy > 0.0f) {
        float inter = __fmul_rn(ix, iy);
        float denom = __fadd_rn(__fsub_rn(__fadd_rn(aA, aB), inter), 1e-6f);
        return __fdiv_rn(inter, denom) > 0.7f;
    }
    return false;
}

// ================= K1: keys + histogram, full-chip wide ======================
__global__ void __launch_bounds__(256)
k_keys_hist(const float* __restrict__ cls) {
    __shared__ int sh[NBUCK];                        // 16 KB
    int t = threadIdx.x;
    for (int k = t; k < NBUCK; k += 256) sh[k] = 0;
    __syncthreads();

    int gi = blockIdx.x * 256 + t;                   // 0 .. 131071
    int b = gi >> 15, i = gi & (NPTS - 1);
    const float* cp = cls + (size_t)gi * NCLS;
    float s = fmaxf(fmaxf(cp[0], cp[1]), cp[2]);
    unsigned u = f2ord(s);
    g_keyfull[b][i] = ((unsigned long long)u << 32) |
                      (unsigned long long)(0xFFFFFFFFu - (unsigned)i);
    atomicAdd(&sh[bucket_of(u)], 1);
    __syncthreads();

    for (int k = t; k < NBUCK; k += 256) {           // block all in one batch
        int v = sh[k];
        if (v) atomicAdd(&g_hist[b][k], v);          // result unused -> RED
    }
}

// ================= K2: per-batch scan+scatter+rank+gather ====================
__global__ void __launch_bounds__(1024)
k_select(const float* __restrict__ boxes, const float* __restrict__ cls) {
    extern __shared__ unsigned char dsm[];
    int* s_cur  = (int*)dsm;                         // 4096 ints (scatter cursors)
    int* s_base = (int*)(dsm + 16384);               // 4096 ints
    unsigned long long* s_keys = (unsigned long long*)(dsm + 32768); // 6144 keys

    __shared__ int s_wsum[32];
    __shared__ int s_wsuf[33];
    __shared__ int s_max;

    int b = blockIdx.x, t = threadIdx.x;
    int lane = t & 31, wrp = t >> 5;
    const float* cb  = cls   + (size_t)b * NPTS * NCLS;
    const float* bx0 = boxes + (size_t)b * NPTS * 7;
    const unsigned long long* kf = g_keyfull[b];

    if (t == 0) s_max = 0;

    // ---- read histogram (coalesced), self-zero for next replay ----
    int h[4];
    int own = 0;
    const int b0 = t * 4;
#pragma unroll
    for (int k = 0; k < 4; k++) { h[k] = g_hist[b][b0 + k]; own += h[k]; }
#pragma unroll
    for (int k = 0; k < 4; k++) g_hist[b][b0 + k] = 0;

    // ---- suffix scan: warp shuffles + one cross-warp step ----
    int v = own;
#pragma unroll
    for (int d = 1; d < 32; d <<= 1) {
        int o = __shfl_down_sync(0xFFFFFFFFu, v, d);
        if (lane + d < 32) v += o;
    }
    if (lane == 0) s_wsum[wrp] = v;
    __syncthreads();
    if (wrp == 0) {
        int wv = s_wsum[lane];
#pragma unroll
        for (int d = 1; d < 32; d <<= 1) {
            int o = __shfl_down_sync(0xFFFFFFFFu, wv, d);
            if (lane + d < 32) wv += o;
        }
        s_wsuf[lane] = wv;                           // sum over warps >= lane
        if (lane == 0) s_wsuf[32] = 0;
    }
    __syncthreads();
    int suffix_incl = v + s_wsuf[wrp + 1];           // sum over threads >= t

    int run = suffix_incl - own;
    int lmax = 0;
#pragma unroll
    for (int k = 3; k >= 0; k--) {
        s_base[b0 + k] = run;
        s_cur[b0 + k]  = run;
        if (run < KSEL && h[k] > 0) {
            int e = run + h[k];
            if (e > lmax) lmax = e;
        }
        run += h[k];
    }
    if (lmax) atomicMax(&s_max, lmax);
    __syncthreads();

    const int candcnt = s_max;
    const int ovf = (candcnt > CAND_CAP);            // adversarial-data fallback
    unsigned long long* keys = ovf ? &g_cand[b][0] : s_keys;

    // ---- scatter precomputed keys, bucket-grouped ----
#pragma unroll 4
    for (int k = 0; k < 32; k++) {
        unsigned long long key = kf[k * 1024 + t];   // coalesced 8B loads
        int bk = bucket_of((unsigned)(key >> 32));
        if (s_base[bk] < KSEL) {
            int pos = atomicAdd(&s_cur[bk], 1);      // pos in [base, base+cnt)
            keys[pos] = key;
        }
    }
    __syncthreads();

    // ---- rank within segment + gather boxes ----
    for (int slot = t; slot < candcnt; slot += 1024) {
        unsigned long long key = keys[slot];
        unsigned u = (unsigned)(key >> 32);
        int bk = bucket_of(u);
        int segbase = s_base[bk];
        if (segbase >= KSEL) continue;               // safety
        int above = (bk > 0) ? s_base[bk - 1] : NPTS;
        int segcnt = above - segbase;
        int rank = segbase;
        if (segcnt > 1) {
            int gt = 0;
#pragma unroll 4
            for (int m = 0; m < segcnt; m++) gt += (keys[segbase + m] > key);
            rank += gt;                              // keys distinct -> unique ranks
        }
        if (rank >= KSEL) continue;

        int idx = (int)(0xFFFFFFFFu - (unsigned)key);
        const float* bx = bx0 + (size_t)idx * 7;
        float v0 = bx[0], v1 = bx[1], v2 = bx[2], v3 = bx[3],
              v4 = bx[4], v5 = bx[5], v6 = bx[6];
        float* ro = &g_rois[b][rank][0];
        ro[0] = v0; ro[1] = v1; ro[2] = v2; ro[3] = v3;
        ro[4] = v4; ro[5] = v5; ro[6] = v6;

        const float* cp = cb + (size_t)idx * NCLS;
        float c0 = cp[0], c1 = cp[1], c2 = cp[2];
        float s = c0; int lab = 0;
        if (c1 > s) { s = c1; lab = 1; }
        if (c2 > s) { s = c2; lab = 2; }
        g_scores[b][rank] = s;
        g_labels[b][rank] = (unsigned char)lab;

        float hx = __fmul_rn(0.5f, v3), hy = __fmul_rn(0.5f, v4);
        float x1 = __fsub_rn(v0, hx), x2 = __fadd_rn(v0, hx);
        float y1 = __fsub_rn(v1, hy), y2 = __fadd_rn(v1, hy);
        g_box4[b][rank] = make_float4(x1, y1, x2, y2);
        g_area[b][rank] = __fmul_rn(v3, v4);
    }
}

// ================= K3: stage-0 suppression mask (broadcast smem) =============
__global__ void __launch_bounds__(64)
k_mask0() {
    int cb = blockIdx.x, rb = blockIdx.y, b = blockIdx.z;
    if (cb < rb) return;

    __shared__ float4 sb[64];
    __shared__ float  sa[64];
    int t = threadIdx.x;
    sb[t] = g_box4[b][cb * 64 + t];
    sa[t] = g_area[b][cb * 64 + t];
    __syncthreads();

    int i = rb * 64 + t;
    float4 me = g_box4[b][i];
    float  a  = g_area[b][i];
    unsigned long long m = 0;
    int j0 = (cb == rb) ? (t + 1) : 0;               // only j > i suppressed
    for (int jj = j0; jj < 64; jj++) {               // sb[jj]: broadcast, conflict-free
        if (iou_gt(me, a, sb[jj], sa[jj])) m |= (1ull << jj);
    }
    g_mask0[b][(size_t)i * NW1 + cb] = m;
}

// ================= K4: single-pass sparse scan + fallback + compact ==========
// Masks copied to padded smem once. rownz[w] = rows with ANY nonzero word
// (one ballot pass). Thread 0 then runs the ENTIRE 16-word greedy with zero
// inner barriers: per accepted nonzero row, OR its full 16-word smem row into
// remv[]; only the diag word feeds the dependent work-update chain.
__global__ void __launch_bounds__(1024)
k_scan_out(float* __restrict__ out) {
    int b = blockIdx.x, tid = threadIdx.x;
    extern __shared__ unsigned char dsm[];
    unsigned long long* ms = (unsigned long long*)dsm;   // stage0: 16*MSW words
    float4* sbox  = (float4*)dsm;                        // fallback alias
    float*  sarea = (float*)(dsm + KSEL * 16);           // fallback alias

    __shared__ unsigned long long remv[NWORDS];
    __shared__ unsigned long long acc_s[NWORDS];
    __shared__ unsigned long long rownz[NW1];
    __shared__ unsigned long long diag[64];              // fallback only
    __shared__ unsigned long long part[1088];            // fallback only
    __shared__ int pref[NWORDS];
    __shared__ int s_fb;

    // zero this batch's output slice early (d_out is poisoned)
    float* rbase = out + b * KPOST * 7;
    for (int e = tid; e < KPOST * 7; e += 1024) rbase[e] = 0.0f;
    if (tid < KPOST) {
        out[SC_OFF + b * KPOST + tid] = 0.0f;
        out[LB_OFF + b * KPOST + tid] = 0.0f;
    }
    if (tid < NWORDS) { remv[tid] = 0ull; acc_s[tid] = 0ull; }
    if (tid < NW1) rownz[tid] = 0ull;

    // ---- bulk copy masks into padded smem (conflict-free layout) ----
    const unsigned long long* M0 = g_mask0[b];
    int r4 = tid >> 4, cw4 = tid & 15;                   // row-in-word, col-word
#pragma unroll
    for (int k = 0; k < NW1; k++)
        ms[k * MSW + r4 * 17 + cw4] = M0[k * 1024 + tid];
    __syncthreads();

    // ---- rownz: rows with any nonzero word, via half-warp ballots ----
    {
        int wid = tid >> 5, lane = tid & 31;             // warp covers rows 2w,2w+1
#pragma unroll
        for (int k = 0; k < NW1; k++) {
            unsigned long long m = ms[k * MSW + r4 * 17 + cw4];
            unsigned bal = __ballot_sync(0xFFFFFFFFu, m != 0ull);
            if (lane == 0) {
                unsigned long long bits =
                    ((bal & 0xFFFFu) ? (1ull << (2 * wid))     : 0ull) |
                    ((bal >> 16)     ? (1ull << (2 * wid + 1)) : 0ull);
                if (bits) atomicOr(&rownz[k], bits);
            }
        }
    }
    __syncthreads();

    // ---- full greedy on thread 0, no inner barriers ----
    if (tid == 0) {
        for (int w = 0; w < NW1; w++) {
            unsigned long long remw = remv[w];
            unsigned long long work = rownz[w] & ~remw;
            while (work) {                               // ~a few rows per word
                int bit = __ffsll((long long)work) - 1;
                const unsigned long long* row = &ms[w * MSW + bit * 17];
                remw |= row[w];                          // diag: dependent chain
#pragma unroll
                for (int cw = 0; cw < NW1; cw++)         // cw<w entries are zero
                    if (cw != w) remv[cw] |= row[cw];    // fire-and-forget RMWs
                work &= ~remw;
                work &= ~(1ull << bit);
            }
            remv[w] = remw;
            acc_s[w] = ~remw;                            // accepted = not suppressed
        }
        int cnt = 0;
        for (int w = 0; w < NW1; w++) cnt += __popcll(acc_s[w]);
        s_fb = (cnt < KPOST);
    }
    __syncthreads();

    // ---------- fallback: full 4096 on-the-fly NMS (never taken normally) ----
    if (s_fb) {
        for (int i = tid; i < KSEL; i += 1024) {         // overwrites ms region
            sbox[i]  = g_box4[b][i];
            sarea[i] = g_area[b][i];
        }
        if (tid < NWORDS) remv[tid] = 0ull;
        __syncthreads();

        int colw = tid >> 4, sub = tid & 15;             // 16 lanes share colw
        for (int w = 0; w < NWORDS; w++) {
            if (tid < 64) {
                int i = w * 64 + tid;
                float4 A = sbox[i]; float aA = sarea[i];
                unsigned long long d = 0ull;
#pragma unroll 1
                for (int j = tid + 1; j < 64; j++) {
                    if (iou_gt(A, aA, sbox[w * 64 + j], sarea[w * 64 + j]))
                        d |= (1ull << j);
                }
                diag[tid] = d;
            }
            __syncthreads();
            if (tid == 0) {
                unsigned long long rem = remv[w], acc = 0ull;
#pragma unroll 1
                for (int bit = 0; bit < 64; bit++) {
                    if (!((rem >> bit) & 1ull)) { acc |= (1ull << bit); rem |= diag[bit]; }
                }
                acc_s[w] = acc;
            }
            __syncthreads();

            unsigned long long acc = acc_s[w];
            unsigned long long p = 0ull;
            if (colw > w) {
#pragma unroll 1
                for (int rr = 0; rr < 4; rr++) {
                    int rbit = sub + rr * 16;
                    if ((acc >> rbit) & 1ull) {
                        int i = w * 64 + rbit;
                        float4 A = sbox[i]; float aA = sarea[i];
#pragma unroll 1
                        for (int j = 0; j < 64; j++) {
                            if (iou_gt(A, aA, sbox[colw * 64 + j], sarea[colw * 64 + j]))
                                p |= (1ull << j);
                        }
                    }
                }
            }
            part[colw * 17 + sub] = p;
            __syncthreads();
            if (tid < 64) {
                unsigned long long vv = remv[tid];
#pragma unroll 1
                for (int k = 0; k < 16; k++) vv |= part[tid * 17 + k];
                remv[tid] = vv;
            }
            __syncthreads();
        }
    }

    // ---------- compact + output ----------
    if (tid == 0) {
        int s = 0;
        for (int w = 0; w < NWORDS; w++) { pref[w] = s; s += __popcll(acc_s[w]); }
    }
    __syncthreads();

    if (tid < NWORDS) {
        unsigned long long a = acc_s[tid];
        int rank = pref[tid];
        while (a && rank < KPOST) {
            int bit = __ffsll((long long)a) - 1;
            a &= a - 1;
            int i = tid * 64 + bit;
            const float* ro = &g_rois[b][i][0];
            int obase = (b * KPOST + rank) * 7;
#pragma unroll
            for (int c = 0; c < 7; c++) out[obase + c] = ro[c];
            out[SC_OFF + b * KPOST + rank] = g_scores[b][i];
            out[LB_OFF + b * KPOST + rank] = (float)(g_labels[b][i] + 1);
            rank++;
        }
    }
}

// ---------------- launch (4 kernels) ----------------
extern "C" void kernel_launch(void* const* d_in, const int* in_sizes, int n_in,
                              void* d_out, int out_size) {
    const float* boxes = (const float*)d_in[0];
    const float* cls   = (const float*)d_in[1];
    if (n_in >= 2 && in_sizes[0] == BATCH * NPTS * NCLS) {
        boxes = (const float*)d_in[1];
        cls   = (const float*)d_in[0];
    }
    float* out = (float*)d_out;

    const int DSM_SEL  = 16384 + 16384 + CAND_CAP * 8;   // 81920 B
    const int DSM_SCAN = NW1 * MSW * 8;                  // 139264 B (masks; >80KB fb)

    cudaFuncSetAttribute(k_select,
                         cudaFuncAttributeMaxDynamicSharedMemorySize, DSM_SEL);
    cudaFuncSetAttribute(k_scan_out,
                         cudaFuncAttributeMaxDynamicSharedMemorySize, DSM_SCAN);

    k_keys_hist<<<BATCH * NPTS / 256, 256>>>(cls);
    k_select<<<BATCH, 1024, DSM_SEL>>>(boxes, cls);
    k_mask0<<<dim3(NW1, NW1, BATCH), 64>>>();
    k_scan_out<<<BATCH, 1024, DSM_SCAN>>>(out);
}

// round 14
// speedup vs baseline: 1.0219x; 1.0219x over previous
#include <cuda_runtime.h>
#include <cuda_bf16.h>

// ---------------- problem constants ----------------
#define BATCH   4
#define NPTS    32768
#define NCLS    3
#define KSEL    4096          // NMS_PRE_MAXSIZE
#define KPOST   512           // NMS_POST_MAXSIZE
#define NWORDS  64            // 4096 / 64
#define NW1     16            // stage-0: first 1024 boxes
#define NBUCK   4096          // fine monotone buckets
#define CAND_CAP 6144         // smem candidate staging capacity

#define ROIS_ELEMS   (BATCH * KPOST * 7)          // 14336
#define SC_OFF       (ROIS_ELEMS)                 // 14336
#define LB_OFF       (ROIS_ELEMS + BATCH * KPOST) // 16384

// ---------------- device scratch (no allocations allowed) ----------------
__device__ int                g_hist[BATCH][NBUCK];         // self-zeroed by k_select
__device__ unsigned long long g_keyfull[BATCH][NPTS];       // 1 MB
__device__ unsigned long long g_cand[BATCH][NPTS];          // overflow path only
__device__ float4             g_box4[BATCH][KSEL];          // x1,y1,x2,y2
__device__ float              g_area[BATCH][KSEL];
__device__ float              g_rois[BATCH][KSEL][7];
__device__ float              g_scores[BATCH][KSEL];
__device__ unsigned char      g_labels[BATCH][KSEL];
__device__ unsigned long long g_mask0[BATCH][1024 * NW1];   // 512 KB [row][word16]
__device__ unsigned long long g_rownz[BATCH][NW1];          // rows with nonzero mask
                                                            // (zeroed by k_select)

// ---------------- helpers ----------------
__device__ __forceinline__ unsigned f2ord(float s) {
    unsigned u = __float_as_uint(s);
    return (u & 0x80000000u) ? ~u : (u | 0x80000000u);
}

// monotone (non-decreasing in u) bucket; fine resolution for s>=0.5
__device__ __forceinline__ int bucket_of(unsigned u) {
    if (u >= 0xBF000000u) {
        unsigned f = 2048u + ((u - 0xBF000000u) >> 12);
        return (int)(f > 4095u ? 4095u : f);
    }
    return (int)(u >> 21);                           // <= 1528 < 2048, monotone
}

// exact-rounding IOU>thresh, identical op order to reference
__device__ __forceinline__ bool iou_gt(float4 A, float aA, float4 B, float aB) {
    float ix = __fsub_rn(fminf(A.z, B.z), fmaxf(A.x, B.x));
    float iy = __fsub_rn(fminf(A.w, B.w), fmaxf(A.y, B.y));
    if (ix > 0.0f && iy > 0.0f) {
        float inter = __fmul_rn(ix, iy);
        float denom = __fadd_rn(__fsub_rn(__fadd_rn(aA, aB), inter), 1e-6f);
        return __fdiv_rn(inter, denom) > 0.7f;
    }
    return false;
}

// ================= K1: keys + histogram, full-chip wide ======================
__global__ void __launch_bounds__(256)
k_keys_hist(const float* __restrict__ cls) {
    __shared__ int sh[NBUCK];                        // 16 KB
    int t = threadIdx.x;
    for (int k = t; k < NBUCK; k += 256) sh[k] = 0;
    __syncthreads();

    int gi = blockIdx.x * 256 + t;                   // 0 .. 131071
    int b = gi >> 15, i = gi & (NPTS - 1);
    const float* cp = cls + (size_t)gi * NCLS;
    float s = fmaxf(fmaxf(cp[0], cp[1]), cp[2]);
    unsigned u = f2ord(s);
    g_keyfull[b][i] = ((unsigned long long)u << 32) |
                      (unsigned long long)(0xFFFFFFFFu - (unsigned)i);
    atomicAdd(&sh[bucket_of(u)], 1);
    __syncthreads();

    for (int k = t; k < NBUCK; k += 256) {           // block all in one batch
        int v = sh[k];
        if (v) atomicAdd(&g_hist[b][k], v);          // result unused -> RED
    }
}

// ================= K2: per-batch scan+scatter+rank+gather ====================
__global__ void __launch_bounds__(1024)
k_select(const float* __restrict__ boxes, const float* __restrict__ cls) {
    extern __shared__ unsigned char dsm[];
    int* s_cur  = (int*)dsm;                         // 4096 ints (scatter cursors)
    int* s_base = (int*)(dsm + 16384);               // 4096 ints
    unsigned long long* s_keys = (unsigned long long*)(dsm + 32768); // 6144 keys

    __shared__ int s_wsum[32];
    __shared__ int s_wsuf[33];
    __shared__ int s_max;

    int b = blockIdx.x, t = threadIdx.x;
    int lane = t & 31, wrp = t >> 5;
    const float* cb  = cls   + (size_t)b * NPTS * NCLS;
    const float* bx0 = boxes + (size_t)b * NPTS * 7;
    const unsigned long long* kf = g_keyfull[b];

    if (t == 0) s_max = 0;
    if (t < NW1) g_rownz[b][t] = 0ull;               // reset for k_mask0's atomicOr

    // ---- read histogram (coalesced), self-zero for next replay ----
    int h[4];
    int own = 0;
    const int b0 = t * 4;
#pragma unroll
    for (int k = 0; k < 4; k++) { h[k] = g_hist[b][b0 + k]; own += h[k]; }
#pragma unroll
    for (int k = 0; k < 4; k++) g_hist[b][b0 + k] = 0;

    // ---- suffix scan: warp shuffles + one cross-warp step ----
    int v = own;
#pragma unroll
    for (int d = 1; d < 32; d <<= 1) {
        int o = __shfl_down_sync(0xFFFFFFFFu, v, d);
        if (lane + d < 32) v += o;
    }
    if (lane == 0) s_wsum[wrp] = v;
    __syncthreads();
    if (wrp == 0) {
        int wv = s_wsum[lane];
#pragma unroll
        for (int d = 1; d < 32; d <<= 1) {
            int o = __shfl_down_sync(0xFFFFFFFFu, wv, d);
            if (lane + d < 32) wv += o;
        }
        s_wsuf[lane] = wv;                           // sum over warps >= lane
        if (lane == 0) s_wsuf[32] = 0;
    }
    __syncthreads();
    int suffix_incl = v + s_wsuf[wrp + 1];           // sum over threads >= t

    int run = suffix_incl - own;
    int lmax = 0;
#pragma unroll
    for (int k = 3; k >= 0; k--) {
        s_base[b0 + k] = run;
        s_cur[b0 + k]  = run;
        if (run < KSEL && h[k] > 0) {
            int e = run + h[k];
            if (e > lmax) lmax = e;
        }
        run += h[k];
    }
    if (lmax) atomicMax(&s_max, lmax);
    __syncthreads();

    const int candcnt = s_max;
    const int ovf = (candcnt > CAND_CAP);            // adversarial-data fallback
    unsigned long long* keys = ovf ? &g_cand[b][0] : s_keys;

    // ---- scatter precomputed keys, bucket-grouped ----
#pragma unroll 4
    for (int k = 0; k < 32; k++) {
        unsigned long long key = kf[k * 1024 + t];   // coalesced 8B loads
        int bk = bucket_of((unsigned)(key >> 32));
        if (s_base[bk] < KSEL) {
            int pos = atomicAdd(&s_cur[bk], 1);      // pos in [base, base+cnt)
            keys[pos] = key;
        }
    }
    __syncthreads();

    // ---- rank within segment + gather boxes ----
    for (int slot = t; slot < candcnt; slot += 1024) {
        unsigned long long key = keys[slot];
        unsigned u = (unsigned)(key >> 32);
        int bk = bucket_of(u);
        int segbase = s_base[bk];
        if (segbase >= KSEL) continue;               // safety
        int above = (bk > 0) ? s_base[bk - 1] : NPTS;
        int segcnt = above - segbase;
        int rank = segbase;
        if (segcnt > 1) {
            int gt = 0;
#pragma unroll 4
            for (int m = 0; m < segcnt; m++) gt += (keys[segbase + m] > key);
            rank += gt;                              // keys distinct -> unique ranks
        }
        if (rank >= KSEL) continue;

        int idx = (int)(0xFFFFFFFFu - (unsigned)key);
        const float* bx = bx0 + (size_t)idx * 7;
        float v0 = bx[0], v1 = bx[1], v2 = bx[2], v3 = bx[3],
              v4 = bx[4], v5 = bx[5], v6 = bx[6];
        float* ro = &g_rois[b][rank][0];
        ro[0] = v0; ro[1] = v1; ro[2] = v2; ro[3] = v3;
        ro[4] = v4; ro[5] = v5; ro[6] = v6;

        const float* cp = cb + (size_t)idx * NCLS;
        float c0 = cp[0], c1 = cp[1], c2 = cp[2];
        float s = c0; int lab = 0;
        if (c1 > s) { s = c1; lab = 1; }
        if (c2 > s) { s = c2; lab = 2; }
        g_scores[b][rank] = s;
        g_labels[b][rank] = (unsigned char)lab;

        float hx = __fmul_rn(0.5f, v3), hy = __fmul_rn(0.5f, v4);
        float x1 = __fsub_rn(v0, hx), x2 = __fadd_rn(v0, hx);
        float y1 = __fsub_rn(v1, hy), y2 = __fadd_rn(v1, hy);
        g_box4[b][rank] = make_float4(x1, y1, x2, y2);
        g_area[b][rank] = __fmul_rn(v3, v4);
    }
}

// ================= K3: stage-0 mask + rownz byproduct ========================
__global__ void __launch_bounds__(64)
k_mask0() {
    int cb = blockIdx.x, rb = blockIdx.y, b = blockIdx.z;
    if (cb < rb) return;

    __shared__ float4 sb[64];
    __shared__ float  sa[64];
    int t = threadIdx.x;
    sb[t] = g_box4[b][cb * 64 + t];
    sa[t] = g_area[b][cb * 64 + t];
    __syncthreads();

    int i = rb * 64 + t;
    float4 me = g_box4[b][i];
    float  a  = g_area[b][i];
    unsigned long long m = 0;
    int j0 = (cb == rb) ? (t + 1) : 0;               // only j > i suppressed
    for (int jj = j0; jj < 64; jj++) {               // sb[jj]: broadcast, conflict-free
        if (iou_gt(me, a, sb[jj], sa[jj])) m |= (1ull << jj);
    }
    g_mask0[b][(size_t)i * NW1 + cb] = m;

    // rownz byproduct: mark rows with any nonzero word (sparse -> rare atomics)
    unsigned bal = __ballot_sync(0xFFFFFFFFu, m != 0ull);
    if ((t & 31) == 0 && bal) {
        unsigned long long bits = (unsigned long long)bal << (t & 32);
        atomicOr(&g_rownz[b][rb], bits);
    }
}

// ================= K4: sparse-gather scan + fallback + compact ===============
// No bulk mask copy: only the ~50 rows flagged in g_rownz gather their 16-word
// mask rows into compacted smem (one 128B line per active thread). Thread-0
// greedy addresses rows via popcount prefix; no inner barriers.
__global__ void __launch_bounds__(1024)
k_scan_out(float* __restrict__ out) {
    int b = blockIdx.x, tid = threadIdx.x;
    extern __shared__ unsigned char dsm[];
    unsigned long long* cm = (unsigned long long*)dsm;   // compacted rows [slot*17+cw]
    float4* sbox  = (float4*)dsm;                        // fallback alias
    float*  sarea = (float*)(dsm + KSEL * 16);           // fallback alias

    __shared__ unsigned long long remv[NWORDS];
    __shared__ unsigned long long acc_s[NWORDS];
    __shared__ unsigned long long rnz[NW1];
    __shared__ unsigned long long diag[64];              // fallback only
    __shared__ unsigned long long part[1088];            // fallback only
    __shared__ int wpre[NW1 + 1];                        // prefix popc of rnz
    __shared__ int pref[NWORDS];
    __shared__ int s_fb;

    // zero this batch's output slice early (d_out is poisoned)
    float* rbase = out + b * KPOST * 7;
    for (int e = tid; e < KPOST * 7; e += 1024) rbase[e] = 0.0f;
    if (tid < KPOST) {
        out[SC_OFF + b * KPOST + tid] = 0.0f;
        out[LB_OFF + b * KPOST + tid] = 0.0f;
    }
    if (tid < NWORDS) { remv[tid] = 0ull; acc_s[tid] = 0ull; }
    if (tid < NW1) rnz[tid] = g_rownz[b][tid];
    __syncthreads();

    if (tid == 0) {                                      // tiny prefix (16 popcs)
        int s = 0;
#pragma unroll
        for (int k = 0; k < NW1; k++) { wpre[k] = s; s += __popcll(rnz[k]); }
        wpre[NW1] = s;
    }
    __syncthreads();
    const int nrows = wpre[NW1];

    // ---- sparse gather: each nonzero row -> one thread -> one 128B line ----
    for (int r = tid; r < NW1 * 64; r += 1024) {
        int w = r >> 6, bit = r & 63;
        if ((rnz[w] >> bit) & 1ull) {
            int slot = wpre[w] + __popcll(rnz[w] & ((bit == 0) ? 0ull
                                   : (~0ull >> (64 - bit))));
            const unsigned long long* src = &g_mask0[b][(size_t)r * NW1];
#pragma unroll
            for (int cw = 0; cw < NW1; cw++)
                cm[slot * 17 + cw] = src[cw];            // 16x8B = one line
        }
    }
    __syncthreads();

    // ---- full greedy on thread 0, compacted rows, no inner barriers ----
    if (tid == 0) {
        for (int w = 0; w < NW1; w++) {
            unsigned long long remw = remv[w];
            unsigned long long work = rnz[w] & ~remw;
            while (work) {                               // ~a few rows per word
                int bit = __ffsll((long long)work) - 1;
                int slot = wpre[w] + __popcll(rnz[w] & ((bit == 0) ? 0ull
                                       : (~0ull >> (64 - bit))));
                const unsigned long long* row = &cm[slot * 17];
                remw |= row[w];                          // diag: dependent chain
#pragma unroll
                for (int cw = 0; cw < NW1; cw++)         // cw<w entries are zero
                    if (cw != w) remv[cw] |= row[cw];
                work &= ~remw;
                work &= ~(1ull << bit);
            }
            remv[w] = remw;
            acc_s[w] = ~remw;                            // accepted = not suppressed
        }
        int cnt = 0;
        for (int w = 0; w < NW1; w++) cnt += __popcll(acc_s[w]);
        s_fb = (cnt < KPOST);
    }
    __syncthreads();

    // ---------- fallback: full 4096 on-the-fly NMS (never taken normally) ----
    if (s_fb) {
        for (int i = tid; i < KSEL; i += 1024) {         // overwrites cm region
            sbox[i]  = g_box4[b][i];
            sarea[i] = g_area[b][i];
        }
        if (tid < NWORDS) remv[tid] = 0ull;
        __syncthreads();

        int colw = tid >> 4, sub = tid & 15;             // 16 lanes share colw
        for (int w = 0; w < NWORDS; w++) {
            if (tid < 64) {
                int i = w * 64 + tid;
                float4 A = sbox[i]; float aA = sarea[i];
                unsigned long long d = 0ull;
#pragma unroll 1
                for (int j = tid + 1; j < 64; j++) {
                    if (iou_gt(A, aA, sbox[w * 64 + j], sarea[w * 64 + j]))
                        d |= (1ull << j);
                }
                diag[tid] = d;
            }
            __syncthreads();
            if (tid == 0) {
                unsigned long long rem = remv[w], acc = 0ull;
#pragma unroll 1
                for (int bit = 0; bit < 64; bit++) {
                    if (!((rem >> bit) & 1ull)) { acc |= (1ull << bit); rem |= diag[bit]; }
                }
                acc_s[w] = acc;
            }
            __syncthreads();

            unsigned long long acc = acc_s[w];
            unsigned long long p = 0ull;
            if (colw > w) {
#pragma unroll 1
                for (int rr = 0; rr < 4; rr++) {
                    int rbit = sub + rr * 16;
                    if ((acc >> rbit) & 1ull) {
                        int i = w * 64 + rbit;
                        float4 A = sbox[i]; float aA = sarea[i];
#pragma unroll 1
                        for (int j = 0; j < 64; j++) {
                            if (iou_gt(A, aA, sbox[colw * 64 + j], sarea[colw * 64 + j]))
                                p |= (1ull << j);
                        }
                    }
                }
            }
            part[colw * 17 + sub] = p;
            __syncthreads();
            if (tid < 64) {
                unsigned long long vv = remv[tid];
#pragma unroll 1
                for (int k = 0; k < 16; k++) vv |= part[tid * 17 + k];
                remv[tid] = vv;
            }
            __syncthreads();
        }
    }

    // ---------- compact + output ----------
    if (tid == 0) {
        int s = 0;
        for (int w = 0; w < NWORDS; w++) { pref[w] = s; s += __popcll(acc_s[w]); }
    }
    __syncthreads();

    if (tid < NWORDS) {
        unsigned long long a = acc_s[tid];
        int rank = pref[tid];
        while (a && rank < KPOST) {
            int bit = __ffsll((long long)a) - 1;
            a &= a - 1;
            int i = tid * 64 + bit;
            const float* ro = &g_rois[b][i][0];
            int obase = (b * KPOST + rank) * 7;
#pragma unroll
            for (int c = 0; c < 7; c++) out[obase + c] = ro[c];
            out[SC_OFF + b * KPOST + rank] = g_scores[b][i];
            out[LB_OFF + b * KPOST + rank] = (float)(g_labels[b][i] + 1);
            rank++;
        }
    }
}

// ---------------- launch (4 kernels) ----------------
extern "C" void kernel_launch(void* const* d_in, const int* in_sizes, int n_in,
                              void* d_out, int out_size) {
    const float* boxes = (const float*)d_in[0];
    const float* cls   = (const float*)d_in[1];
    if (n_in >= 2 && in_sizes[0] == BATCH * NPTS * NCLS) {
        boxes = (const float*)d_in[1];
        cls   = (const float*)d_in[0];
    }
    float* out = (float*)d_out;

    const int DSM_SEL  = 16384 + 16384 + CAND_CAP * 8;   // 81920 B
    const int DSM_SCAN = 1024 * 17 * 8;                  // 139264 B (worst-case rows)

    cudaFuncSetAttribute(k_select,
                         cudaFuncAttributeMaxDynamicSharedMemorySize, DSM_SEL);
    cudaFuncSetAttribute(k_scan_out,
                         cudaFuncAttributeMaxDynamicSharedMemorySize, DSM_SCAN);

    k_keys_hist<<<BATCH * NPTS / 256, 256>>>(cls);
    k_select<<<BATCH, 1024, DSM_SEL>>>(boxes, cls);
    k_mask0<<<dim3(NW1, NW1, BATCH), 64>>>();
    k_scan_out<<<BATCH, 1024, DSM_SCAN>>>(out);
}

// round 15
// speedup vs baseline: 1.5964x; 1.5621x over previous
#include <cuda_runtime.h>
#include <cuda_bf16.h>

// ---------------- problem constants ----------------
#define BATCH   4
#define NPTS    32768
#define NCLS    3
#define KSEL    4096          // NMS_PRE_MAXSIZE
#define KPOST   512           // NMS_POST_MAXSIZE
#define NWORDS  64            // 4096 / 64
#define NW1     16            // stage-0: first 1024 boxes
#define NBUCK   4096          // fine monotone buckets
#define CAND_CAP 6144         // smem candidate staging capacity
#define NCAP    320           // compacted-row smem capacity (scan_out)

#define ROIS_ELEMS   (BATCH * KPOST * 7)          // 14336
#define SC_OFF       (ROIS_ELEMS)                 // 14336
#define LB_OFF       (ROIS_ELEMS + BATCH * KPOST) // 16384

// ---------------- device scratch (no allocations allowed) ----------------
__device__ int                g_hist[BATCH][NBUCK];         // self-zeroed by k_select
__device__ unsigned long long g_keyfull[BATCH][NPTS];       // 1 MB
__device__ unsigned long long g_cand[BATCH][NPTS];          // overflow path only
__device__ float4             g_box4[BATCH][KSEL];          // x1,y1,x2,y2
__device__ float              g_area[BATCH][KSEL];
__device__ float              g_rois[BATCH][KSEL][7];
__device__ float              g_scores[BATCH][KSEL];
__device__ unsigned char      g_labels[BATCH][KSEL];
__device__ unsigned long long g_mask0[BATCH][1024 * NW1];   // 512 KB [row][word16]
__device__ unsigned long long g_rownz[BATCH][NW1];          // rows with nonzero mask
                                                            // (zeroed by k_select)

// ---------------- helpers ----------------
__device__ __forceinline__ unsigned f2ord(float s) {
    unsigned u = __float_as_uint(s);
    return (u & 0x80000000u) ? ~u : (u | 0x80000000u);
}

// monotone (non-decreasing in u) bucket; fine resolution for s>=0.5
__device__ __forceinline__ int bucket_of(unsigned u) {
    if (u >= 0xBF000000u) {
        unsigned f = 2048u + ((u - 0xBF000000u) >> 12);
        return (int)(f > 4095u ? 4095u : f);
    }
    return (int)(u >> 21);                           // <= 1528 < 2048, monotone
}

__device__ __forceinline__ unsigned long long below_mask(int bit) {
    return (bit == 0) ? 0ull : (~0ull >> (64 - bit));
}

// exact-rounding IOU>thresh, identical op order to reference
__device__ __forceinline__ bool iou_gt(float4 A, float aA, float4 B, float aB) {
    float ix = __fsub_rn(fminf(A.z, B.z), fmaxf(A.x, B.x));
    float iy = __fsub_rn(fminf(A.w, B.w), fmaxf(A.y, B.y));
    if (ix > 0.0f && iy > 0.0f) {
        float inter = __fmul_rn(ix, iy);
        float denom = __fadd_rn(__fsub_rn(__fadd_rn(aA, aB), inter), 1e-6f);
        return __fdiv_rn(inter, denom) > 0.7f;
    }
    return false;
}

// ================= K1: keys + histogram, full-chip wide ======================
__global__ void __launch_bounds__(256)
k_keys_hist(const float* __restrict__ cls) {
    __shared__ int sh[NBUCK];                        // 16 KB
    int t = threadIdx.x;
    for (int k = t; k < NBUCK; k += 256) sh[k] = 0;
    __syncthreads();

    int gi = blockIdx.x * 256 + t;                   // 0 .. 131071
    int b = gi >> 15, i = gi & (NPTS - 1);
    const float* cp = cls + (size_t)gi * NCLS;
    float s = fmaxf(fmaxf(cp[0], cp[1]), cp[2]);
    unsigned u = f2ord(s);
    g_keyfull[b][i] = ((unsigned long long)u << 32) |
                      (unsigned long long)(0xFFFFFFFFu - (unsigned)i);
    atomicAdd(&sh[bucket_of(u)], 1);
    __syncthreads();

    for (int k = t; k < NBUCK; k += 256) {           // block all in one batch
        int v = sh[k];
        if (v) atomicAdd(&g_hist[b][k], v);          // result unused -> RED
    }
}

// ================= K2: per-batch scan+scatter+rank+gather ====================
__global__ void __launch_bounds__(1024)
k_select(const float* __restrict__ boxes, const float* __restrict__ cls) {
    extern __shared__ unsigned char dsm[];
    int* s_cur  = (int*)dsm;                         // 4096 ints (scatter cursors)
    int* s_base = (int*)(dsm + 16384);               // 4096 ints
    unsigned long long* s_keys = (unsigned long long*)(dsm + 32768); // 6144 keys

    __shared__ int s_wsum[32];
    __shared__ int s_wsuf[33];
    __shared__ int s_max;

    int b = blockIdx.x, t = threadIdx.x;
    int lane = t & 31, wrp = t >> 5;
    const float* cb  = cls   + (size_t)b * NPTS * NCLS;
    const float* bx0 = boxes + (size_t)b * NPTS * 7;
    const unsigned long long* kf = g_keyfull[b];

    if (t == 0) s_max = 0;
    if (t < NW1) g_rownz[b][t] = 0ull;               // reset for k_mask0's atomicOr

    // ---- read histogram (coalesced), self-zero for next replay ----
    int h[4];
    int own = 0;
    const int b0 = t * 4;
#pragma unroll
    for (int k = 0; k < 4; k++) { h[k] = g_hist[b][b0 + k]; own += h[k]; }
#pragma unroll
    for (int k = 0; k < 4; k++) g_hist[b][b0 + k] = 0;

    // ---- suffix scan: warp shuffles + one cross-warp step ----
    int v = own;
#pragma unroll
    for (int d = 1; d < 32; d <<= 1) {
        int o = __shfl_down_sync(0xFFFFFFFFu, v, d);
        if (lane + d < 32) v += o;
    }
    if (lane == 0) s_wsum[wrp] = v;
    __syncthreads();
    if (wrp == 0) {
        int wv = s_wsum[lane];
#pragma unroll
        for (int d = 1; d < 32; d <<= 1) {
            int o = __shfl_down_sync(0xFFFFFFFFu, wv, d);
            if (lane + d < 32) wv += o;
        }
        s_wsuf[lane] = wv;                           // sum over warps >= lane
        if (lane == 0) s_wsuf[32] = 0;
    }
    __syncthreads();
    int suffix_incl = v + s_wsuf[wrp + 1];           // sum over threads >= t

    int run = suffix_incl - own;
    int lmax = 0;
#pragma unroll
    for (int k = 3; k >= 0; k--) {
        s_base[b0 + k] = run;
        s_cur[b0 + k]  = run;
        if (run < KSEL && h[k] > 0) {
            int e = run + h[k];
            if (e > lmax) lmax = e;
        }
        run += h[k];
    }
    if (lmax) atomicMax(&s_max, lmax);
    __syncthreads();

    const int candcnt = s_max;
    const int ovf = (candcnt > CAND_CAP);            // adversarial-data fallback
    unsigned long long* keys = ovf ? &g_cand[b][0] : s_keys;

    // ---- scatter precomputed keys, bucket-grouped ----
#pragma unroll 4
    for (int k = 0; k < 32; k++) {
        unsigned long long key = kf[k * 1024 + t];   // coalesced 8B loads
        int bk = bucket_of((unsigned)(key >> 32));
        if (s_base[bk] < KSEL) {
            int pos = atomicAdd(&s_cur[bk], 1);      // pos in [base, base+cnt)
            keys[pos] = key;
        }
    }
    __syncthreads();

    // ---- rank within segment + gather boxes ----
    for (int slot = t; slot < candcnt; slot += 1024) {
        unsigned long long key = keys[slot];
        unsigned u = (unsigned)(key >> 32);
        int bk = bucket_of(u);
        int segbase = s_base[bk];
        if (segbase >= KSEL) continue;               // safety
        int above = (bk > 0) ? s_base[bk - 1] : NPTS;
        int segcnt = above - segbase;
        int rank = segbase;
        if (segcnt > 1) {
            int gt = 0;
#pragma unroll 4
            for (int m = 0; m < segcnt; m++) gt += (keys[segbase + m] > key);
            rank += gt;                              // keys distinct -> unique ranks
        }
        if (rank >= KSEL) continue;

        int idx = (int)(0xFFFFFFFFu - (unsigned)key);
        const float* bx = bx0 + (size_t)idx * 7;
        float v0 = bx[0], v1 = bx[1], v2 = bx[2], v3 = bx[3],
              v4 = bx[4], v5 = bx[5], v6 = bx[6];
        float* ro = &g_rois[b][rank][0];
        ro[0] = v0; ro[1] = v1; ro[2] = v2; ro[3] = v3;
        ro[4] = v4; ro[5] = v5; ro[6] = v6;

        const float* cp = cb + (size_t)idx * NCLS;
        float c0 = cp[0], c1 = cp[1], c2 = cp[2];
        float s = c0; int lab = 0;
        if (c1 > s) { s = c1; lab = 1; }
        if (c2 > s) { s = c2; lab = 2; }
        g_scores[b][rank] = s;
        g_labels[b][rank] = (unsigned char)lab;

        float hx = __fmul_rn(0.5f, v3), hy = __fmul_rn(0.5f, v4);
        float x1 = __fsub_rn(v0, hx), x2 = __fadd_rn(v0, hx);
        float y1 = __fsub_rn(v1, hy), y2 = __fadd_rn(v1, hy);
        g_box4[b][rank] = make_float4(x1, y1, x2, y2);
        g_area[b][rank] = __fmul_rn(v3, v4);
    }
}

// ================= K3: stage-0 mask + rownz byproduct ========================
__global__ void __launch_bounds__(64)
k_mask0() {
    int cb = blockIdx.x, rb = blockIdx.y, b = blockIdx.z;
    if (cb < rb) return;

    __shared__ float4 sb[64];
    __shared__ float  sa[64];
    int t = threadIdx.x;
    sb[t] = g_box4[b][cb * 64 + t];
    sa[t] = g_area[b][cb * 64 + t];
    __syncthreads();

    int i = rb * 64 + t;
    float4 me = g_box4[b][i];
    float  a  = g_area[b][i];
    unsigned long long m = 0;
    int j0 = (cb == rb) ? (t + 1) : 0;               // only j > i suppressed
    for (int jj = j0; jj < 64; jj++) {               // sb[jj]: broadcast, conflict-free
        if (iou_gt(me, a, sb[jj], sa[jj])) m |= (1ull << jj);
    }
    g_mask0[b][(size_t)i * NW1 + cb] = m;

    // rownz byproduct: mark rows with any nonzero word (sparse -> rare atomics)
    unsigned bal = __ballot_sync(0xFFFFFFFFu, m != 0ull);
    if ((t & 31) == 0 && bal) {
        unsigned long long bits = (unsigned long long)bal << (t & 32);
        atomicOr(&g_rownz[b][rb], bits);
    }
}

// ================= K4: register-greedy scan + parallel compact ===============
// Sparse gather of nonzero rows into smem (cap NCAP; global path beyond).
// Thread-0 greedy keeps rem[16] in REGISTERS (fully unrolled) -> ~120cy/row.
// Output: one thread per box computes its own rank (parallel compact).
__global__ void __launch_bounds__(1024)
k_scan_out(float* __restrict__ out) {
    int b = blockIdx.x, tid = threadIdx.x;
    extern __shared__ unsigned char dsm[];
    unsigned long long* cm = (unsigned long long*)dsm;   // compacted rows [slot*17+cw]

    __shared__ unsigned long long rnz[NW1];
    __shared__ unsigned long long acc_s[NWORDS];
    __shared__ unsigned long long remv[NWORDS];          // fallback only
    __shared__ unsigned long long diag[64];              // fallback only
    __shared__ unsigned long long part[1088];            // fallback only
    __shared__ int s_fb;

    // zero this batch's output slice early (d_out is poisoned)
    float* rbase = out + b * KPOST * 7;
    for (int e = tid; e < KPOST * 7; e += 1024) rbase[e] = 0.0f;
    if (tid < KPOST) {
        out[SC_OFF + b * KPOST + tid] = 0.0f;
        out[LB_OFF + b * KPOST + tid] = 0.0f;
    }
    if (tid < NWORDS) acc_s[tid] = 0ull;
    if (tid < NW1) rnz[tid] = g_rownz[b][tid];
    __syncthreads();

    // per-thread nrows (cheap: 16 smem popcs, broadcast reads)
    int nrows = 0;
#pragma unroll
    for (int k = 0; k < NW1; k++) nrows += __popcll(rnz[k]);
    const bool use_smem = (nrows <= NCAP);

    // ---- sparse gather: each nonzero row -> one thread -> one 128B line ----
    if (use_smem && tid < NW1 * 64) {
        int w = tid >> 6, bit = tid & 63;
        if ((rnz[w] >> bit) & 1ull) {
            int slot = 0;
            for (int k = 0; k < w; k++) slot += __popcll(rnz[k]);
            slot += __popcll(rnz[w] & below_mask(bit));
            const unsigned long long* src = &g_mask0[b][(size_t)tid * NW1];
#pragma unroll
            for (int cw = 0; cw < NW1; cw++)
                cm[slot * 17 + cw] = src[cw];            // 16x8B = one line
        }
    }
    __syncthreads();

    // ---- thread-0 greedy: rem[] in registers, no smem RMW ----
    if (tid == 0) {
        unsigned long long rem[NW1];
#pragma unroll
        for (int k = 0; k < NW1; k++) rem[k] = 0ull;
        int base = 0;
#pragma unroll
        for (int w = 0; w < NW1; w++) {                  // full unroll: rem[] in regs
            unsigned long long rnzw = rnz[w];
            unsigned long long remw = rem[w];
            unsigned long long work = rnzw & ~remw;
            while (work) {                               // ~a few rows per word
                int bit = __ffsll((long long)work) - 1;
                const unsigned long long* row;
                if (use_smem) {
                    int slot = base + __popcll(rnzw & below_mask(bit));
                    row = &cm[slot * 17];
                } else {                                 // adversarial path
                    row = &g_mask0[b][(size_t)(w * 64 + bit) * NW1];
                }
                remw |= row[w];                          // diag: dependent chain
#pragma unroll
                for (int cw = 0; cw < NW1; cw++)         // cw<w entries are zero
                    if (cw != w) rem[cw] |= row[cw];     // register ORs
                work &= ~remw;
                work &= ~(1ull << bit);
            }
            rem[w] = remw;
            acc_s[w] = ~remw;                            // accepted = not suppressed
            base += __popcll(rnzw);
        }
        int cnt = 0;
#pragma unroll
        for (int w = 0; w < NW1; w++) cnt += __popcll(~rem[w]);
        s_fb = (cnt < KPOST);
    }
    __syncthreads();

    // ---------- fallback: full 4096 NMS, boxes from GLOBAL (never taken) -----
    if (s_fb) {
        if (tid < NWORDS) remv[tid] = 0ull;
        __syncthreads();

        int colw = tid >> 4, sub = tid & 15;             // 16 lanes share colw
        for (int w = 0; w < NWORDS; w++) {
            if (tid < 64) {
                int i = w * 64 + tid;
                float4 A = g_box4[b][i]; float aA = g_area[b][i];
                unsigned long long d = 0ull;
#pragma unroll 1
                for (int j = tid + 1; j < 64; j++) {
                    int j2 = w * 64 + j;
                    if (iou_gt(A, aA, g_box4[b][j2], g_area[b][j2]))
                        d |= (1ull << j);
                }
                diag[tid] = d;
            }
            __syncthreads();
            if (tid == 0) {
                unsigned long long rem = remv[w], acc = 0ull;
#pragma unroll 1
                for (int bit = 0; bit < 64; bit++) {
                    if (!((rem >> bit) & 1ull)) { acc |= (1ull << bit); rem |= diag[bit]; }
                }
                acc_s[w] = acc;
            }
            __syncthreads();

            unsigned long long acc = acc_s[w];
            unsigned long long p = 0ull;
            if (colw > w) {
#pragma unroll 1
                for (int rr = 0; rr < 4; rr++) {
                    int rbit = sub + rr * 16;
                    if ((acc >> rbit) & 1ull) {
                        int i = w * 64 + rbit;
                        float4 A = g_box4[b][i]; float aA = g_area[b][i];
#pragma unroll 1
                        for (int j = 0; j < 64; j++) {
                            int j2 = colw * 64 + j;
                            if (iou_gt(A, aA, g_box4[b][j2], g_area[b][j2]))
                                p |= (1ull << j);
                        }
                    }
                }
            }
            part[colw * 17 + sub] = p;
            __syncthreads();
            if (tid < 64) {
                unsigned long long vv = remv[tid];
#pragma unroll 1
                for (int k = 0; k < 16; k++) vv |= part[tid * 17 + k];
                remv[tid] = vv;
            }
            __syncthreads();
        }
    }

    // ---------- parallel compact: one thread per box computes its rank -------
    for (int r = tid; r < KSEL; r += 1024) {
        int w = r >> 6, bit = r & 63;
        unsigned long long acc = acc_s[w];
        if ((acc >> bit) & 1ull) {
            int rank = 0;
            for (int k = 0; k < w; k++) rank += __popcll(acc_s[k]);
            rank += __popcll(acc & below_mask(bit));
            if (rank < KPOST) {
                const float* ro = &g_rois[b][r][0];
                int obase = (b * KPOST + rank) * 7;
#pragma unroll
                for (int c = 0; c < 7; c++) out[obase + c] = ro[c];
                out[SC_OFF + b * KPOST + rank] = g_scores[b][r];
                out[LB_OFF + b * KPOST + rank] = (float)(g_labels[b][r] + 1);
            }
        }
    }
}

// ---------------- launch (4 kernels) ----------------
extern "C" void kernel_launch(void* const* d_in, const int* in_sizes, int n_in,
                              void* d_out, int out_size) {
    const float* boxes = (const float*)d_in[0];
    const float* cls   = (const float*)d_in[1];
    if (n_in >= 2 && in_sizes[0] == BATCH * NPTS * NCLS) {
        boxes = (const float*)d_in[1];
        cls   = (const float*)d_in[0];
    }
    float* out = (float*)d_out;

    const int DSM_SEL  = 16384 + 16384 + CAND_CAP * 8;   // 81920 B
    const int DSM_SCAN = NCAP * 17 * 8;                  // 43520 B

    cudaFuncSetAttribute(k_select,
                         cudaFuncAttributeMaxDynamicSharedMemorySize, DSM_SEL);
    cudaFuncSetAttribute(k_scan_out,
                         cudaFuncAttributeMaxDynamicSharedMemorySize, DSM_SCAN);

    k_keys_hist<<<BATCH * NPTS / 256, 256>>>(cls);
    k_select<<<BATCH, 1024, DSM_SEL>>>(boxes, cls);
    k_mask0<<<dim3(NW1, NW1, BATCH), 64>>>();
    k_scan_out<<<BATCH, 1024, DSM_SCAN>>>(out);
}

// round 16
// speedup vs baseline: 1.5997x; 1.0021x over previous
#include <cuda_runtime.h>
#include <cuda_bf16.h>

// ---------------- problem constants ----------------
#define BATCH   4
#define NPTS    32768
#define NCLS    3
#define KSEL    4096          // NMS_PRE_MAXSIZE
#define KPOST   512           // NMS_POST_MAXSIZE
#define NWORDS  64            // 4096 / 64
#define NW1     16            // stage-0: first 1024 boxes
#define NBUCK   4096          // fine monotone buckets
#define CAND_CAP 6144         // smem candidate staging capacity
#define NCAP    320           // compacted-row smem capacity (scan_out)

#define ROIS_ELEMS   (BATCH * KPOST * 7)          // 14336
#define SC_OFF       (ROIS_ELEMS)                 // 14336
#define LB_OFF       (ROIS_ELEMS + BATCH * KPOST) // 16384
#define OUT_TOTAL    (ROIS_ELEMS + 2 * BATCH * KPOST) // 18432

// ---------------- device scratch (no allocations allowed) ----------------
__device__ int                g_hist[BATCH][NBUCK];         // self-zeroed by k_select
__device__ unsigned long long g_keyfull[BATCH][NPTS];       // 1 MB
__device__ unsigned long long g_cand[BATCH][NPTS];          // overflow path only
__device__ float4             g_box4[BATCH][KSEL];          // x1,y1,x2,y2
__device__ float              g_area[BATCH][KSEL];
__device__ float              g_rois[BATCH][KSEL][7];
__device__ float              g_scores[BATCH][KSEL];
__device__ unsigned char      g_labels[BATCH][KSEL];
__device__ unsigned long long g_mask0[BATCH][1024 * NW1];   // 512 KB [row][word16]
__device__ unsigned long long g_rownz[BATCH][NW1];          // rows with nonzero mask
                                                            // (zeroed by k_select)

// ---------------- helpers ----------------
__device__ __forceinline__ unsigned f2ord(float s) {
    unsigned u = __float_as_uint(s);
    return (u & 0x80000000u) ? ~u : (u | 0x80000000u);
}

// monotone (non-decreasing in u) bucket; fine resolution for s>=0.5
__device__ __forceinline__ int bucket_of(unsigned u) {
    if (u >= 0xBF000000u) {
        unsigned f = 2048u + ((u - 0xBF000000u) >> 12);
        return (int)(f > 4095u ? 4095u : f);
    }
    return (int)(u >> 21);                           // <= 1528 < 2048, monotone
}

__device__ __forceinline__ unsigned long long below_mask(int bit) {
    return (bit == 0) ? 0ull : (~0ull >> (64 - bit));
}

// exact-rounding IOU>thresh, identical op order to reference
__device__ __forceinline__ bool iou_gt(float4 A, float aA, float4 B, float aB) {
    float ix = __fsub_rn(fminf(A.z, B.z), fmaxf(A.x, B.x));
    float iy = __fsub_rn(fminf(A.w, B.w), fmaxf(A.y, B.y));
    if (ix > 0.0f && iy > 0.0f) {
        float inter = __fmul_rn(ix, iy);
        float denom = __fadd_rn(__fsub_rn(__fadd_rn(aA, aB), inter), 1e-6f);
        return __fdiv_rn(inter, denom) > 0.7f;
    }
    return false;
}

// ================= K1: keys + direct-RED histogram + output zeroing ==========
// Wide (512x256). No smem histogram: one result-unused atomicAdd per element
// (RED at L2; fine buckets spread contention to ~8K addresses).
// Also zeroes the poisoned output buffer (independent work, free here).
__global__ void __launch_bounds__(256)
k_keys_hist(const float* __restrict__ cls, float* __restrict__ out) {
    int gi = blockIdx.x * 256 + threadIdx.x;         // 0 .. 131071
    int b = gi >> 15, i = gi & (NPTS - 1);
    const float* cp = cls + (size_t)gi * NCLS;
    float s = fmaxf(fmaxf(cp[0], cp[1]), cp[2]);
    unsigned u = f2ord(s);
    g_keyfull[b][i] = ((unsigned long long)u << 32) |
                      (unsigned long long)(0xFFFFFFFFu - (unsigned)i);
    atomicAdd(&g_hist[b][bucket_of(u)], 1);          // result unused -> RED

    // zero output slice (d_out poisoned); OUT_TOTAL=18432 < gridDim*blockDim
    if (gi < OUT_TOTAL) out[gi] = 0.0f;
}

// ================= K2: per-batch scan+scatter+rank+gather ====================
__global__ void __launch_bounds__(1024)
k_select(const float* __restrict__ boxes, const float* __restrict__ cls) {
    extern __shared__ unsigned char dsm[];
    int* s_cur  = (int*)dsm;                         // 4096 ints (scatter cursors)
    int* s_base = (int*)(dsm + 16384);               // 4096 ints
    unsigned long long* s_keys = (unsigned long long*)(dsm + 32768); // 6144 keys

    __shared__ int s_wsum[32];
    __shared__ int s_wsuf[33];
    __shared__ int s_max;

    int b = blockIdx.x, t = threadIdx.x;
    int lane = t & 31, wrp = t >> 5;
    const float* cb  = cls   + (size_t)b * NPTS * NCLS;
    const float* bx0 = boxes + (size_t)b * NPTS * 7;
    const unsigned long long* kf = g_keyfull[b];

    if (t == 0) s_max = 0;
    if (t < NW1) g_rownz[b][t] = 0ull;               // reset for k_mask0's atomicOr

    // ---- read histogram (coalesced), self-zero for next replay ----
    int h[4];
    int own = 0;
    const int b0 = t * 4;
#pragma unroll
    for (int k = 0; k < 4; k++) { h[k] = g_hist[b][b0 + k]; own += h[k]; }
#pragma unroll
    for (int k = 0; k < 4; k++) g_hist[b][b0 + k] = 0;

    // ---- suffix scan: warp shuffles + one cross-warp step ----
    int v = own;
#pragma unroll
    for (int d = 1; d < 32; d <<= 1) {
        int o = __shfl_down_sync(0xFFFFFFFFu, v, d);
        if (lane + d < 32) v += o;
    }
    if (lane == 0) s_wsum[wrp] = v;
    __syncthreads();
    if (wrp == 0) {
        int wv = s_wsum[lane];
#pragma unroll
        for (int d = 1; d < 32; d <<= 1) {
            int o = __shfl_down_sync(0xFFFFFFFFu, wv, d);
            if (lane + d < 32) wv += o;
        }
        s_wsuf[lane] = wv;                           // sum over warps >= lane
        if (lane == 0) s_wsuf[32] = 0;
    }
    __syncthreads();
    int suffix_incl = v + s_wsuf[wrp + 1];           // sum over threads >= t

    int run = suffix_incl - own;
    int lmax = 0;
#pragma unroll
    for (int k = 3; k >= 0; k--) {
        s_base[b0 + k] = run;
        s_cur[b0 + k]  = run;
        if (run < KSEL && h[k] > 0) {
            int e = run + h[k];
            if (e > lmax) lmax = e;
        }
        run += h[k];
    }
    if (lmax) atomicMax(&s_max, lmax);
    __syncthreads();

    const int candcnt = s_max;
    const int ovf = (candcnt > CAND_CAP);            // adversarial-data fallback
    unsigned long long* keys = ovf ? &g_cand[b][0] : s_keys;

    // ---- scatter precomputed keys, bucket-grouped ----
#pragma unroll 4
    for (int k = 0; k < 32; k++) {
        unsigned long long key = kf[k * 1024 + t];   // coalesced 8B loads
        int bk = bucket_of((unsigned)(key >> 32));
        if (s_base[bk] < KSEL) {
            int pos = atomicAdd(&s_cur[bk], 1);      // pos in [base, base+cnt)
            keys[pos] = key;
        }
    }
    __syncthreads();

    // ---- rank within segment + gather boxes ----
    for (int slot = t; slot < candcnt; slot += 1024) {
        unsigned long long key = keys[slot];
        unsigned u = (unsigned)(key >> 32);
        int bk = bucket_of(u);
        int segbase = s_base[bk];
        if (segbase >= KSEL) continue;               // safety
        int above = (bk > 0) ? s_base[bk - 1] : NPTS;
        int segcnt = above - segbase;
        int rank = segbase;
        if (segcnt > 1) {
            int gt = 0;
#pragma unroll 4
            for (int m = 0; m < segcnt; m++) gt += (keys[segbase + m] > key);
            rank += gt;                              // keys distinct -> unique ranks
        }
        if (rank >= KSEL) continue;

        int idx = (int)(0xFFFFFFFFu - (unsigned)key);
        const float* bx = bx0 + (size_t)idx * 7;
        float v0 = bx[0], v1 = bx[1], v2 = bx[2], v3 = bx[3],
              v4 = bx[4], v5 = bx[5], v6 = bx[6];
        float* ro = &g_rois[b][rank][0];
        ro[0] = v0; ro[1] = v1; ro[2] = v2; ro[3] = v3;
        ro[4] = v4; ro[5] = v5; ro[6] = v6;

        const float* cp = cb + (size_t)idx * NCLS;
        float c0 = cp[0], c1 = cp[1], c2 = cp[2];
        float s = c0; int lab = 0;
        if (c1 > s) { s = c1; lab = 1; }
        if (c2 > s) { s = c2; lab = 2; }
        g_scores[b][rank] = s;
        g_labels[b][rank] = (unsigned char)lab;

        float hx = __fmul_rn(0.5f, v3), hy = __fmul_rn(0.5f, v4);
        float x1 = __fsub_rn(v0, hx), x2 = __fadd_rn(v0, hx);
        float y1 = __fsub_rn(v1, hy), y2 = __fadd_rn(v1, hy);
        g_box4[b][rank] = make_float4(x1, y1, x2, y2);
        g_area[b][rank] = __fmul_rn(v3, v4);
    }
}

// ================= K3: stage-0 mask + rownz byproduct ========================
__global__ void __launch_bounds__(64)
k_mask0() {
    int cb = blockIdx.x, rb = blockIdx.y, b = blockIdx.z;
    if (cb < rb) return;

    __shared__ float4 sb[64];
    __shared__ float  sa[64];
    int t = threadIdx.x;
    sb[t] = g_box4[b][cb * 64 + t];
    sa[t] = g_area[b][cb * 64 + t];
    __syncthreads();

    int i = rb * 64 + t;
    float4 me = g_box4[b][i];
    float  a  = g_area[b][i];
    unsigned long long m = 0;
    int j0 = (cb == rb) ? (t + 1) : 0;               // only j > i suppressed
    for (int jj = j0; jj < 64; jj++) {               // sb[jj]: broadcast, conflict-free
        if (iou_gt(me, a, sb[jj], sa[jj])) m |= (1ull << jj);
    }
    g_mask0[b][(size_t)i * NW1 + cb] = m;

    // rownz byproduct: mark rows with any nonzero word (sparse -> rare atomics)
    unsigned bal = __ballot_sync(0xFFFFFFFFu, m != 0ull);
    if ((t & 31) == 0 && bal) {
        unsigned long long bits = (unsigned long long)bal << (t & 32);
        atomicOr(&g_rownz[b][rb], bits);
    }
}

// ================= K4: register-greedy scan + parallel compact ===============
__global__ void __launch_bounds__(1024)
k_scan_out(float* __restrict__ out) {
    int b = blockIdx.x, tid = threadIdx.x;
    extern __shared__ unsigned char dsm[];
    unsigned long long* cm = (unsigned long long*)dsm;   // compacted rows [slot*17+cw]

    __shared__ unsigned long long rnz[NW1];
    __shared__ unsigned long long acc_s[NWORDS];
    __shared__ unsigned long long remv[NWORDS];          // fallback only
    __shared__ unsigned long long diag[64];              // fallback only
    __shared__ unsigned long long part[1088];            // fallback only
    __shared__ int s_fb;

    if (tid < NWORDS) acc_s[tid] = 0ull;
    if (tid < NW1) rnz[tid] = g_rownz[b][tid];
    __syncthreads();

    // per-thread nrows (cheap: 16 smem popcs, broadcast reads)
    int nrows = 0;
#pragma unroll
    for (int k = 0; k < NW1; k++) nrows += __popcll(rnz[k]);
    const bool use_smem = (nrows <= NCAP);

    // ---- sparse gather: each nonzero row -> one thread -> one 128B line ----
    if (use_smem && tid < NW1 * 64) {
        int w = tid >> 6, bit = tid & 63;
        if ((rnz[w] >> bit) & 1ull) {
            int slot = 0;
            for (int k = 0; k < w; k++) slot += __popcll(rnz[k]);
            slot += __popcll(rnz[w] & below_mask(bit));
            const unsigned long long* src = &g_mask0[b][(size_t)tid * NW1];
#pragma unroll
            for (int cw = 0; cw < NW1; cw++)
                cm[slot * 17 + cw] = src[cw];            // 16x8B = one line
        }
    }
    __syncthreads();

    // ---- thread-0 greedy: rem[] in registers, no smem RMW ----
    if (tid == 0) {
        unsigned long long rem[NW1];
#pragma unroll
        for (int k = 0; k < NW1; k++) rem[k] = 0ull;
        int base = 0;
#pragma unroll
        for (int w = 0; w < NW1; w++) {                  // full unroll: rem[] in regs
            unsigned long long rnzw = rnz[w];
            unsigned long long remw = rem[w];
            unsigned long long work = rnzw & ~remw;
            while (work) {                               // ~a few rows per word
                int bit = __ffsll((long long)work) - 1;
                const unsigned long long* row;
                if (use_smem) {
                    int slot = base + __popcll(rnzw & below_mask(bit));
                    row = &cm[slot * 17];
                } else {                                 // adversarial path
                    row = &g_mask0[b][(size_t)(w * 64 + bit) * NW1];
                }
                remw |= row[w];                          // diag: dependent chain
#pragma unroll
                for (int cw = 0; cw < NW1; cw++)         // cw<w entries are zero
                    if (cw != w) rem[cw] |= row[cw];     // register ORs
                work &= ~remw;
                work &= ~(1ull << bit);
            }
            rem[w] = remw;
            acc_s[w] = ~remw;                            // accepted = not suppressed
            base += __popcll(rnzw);
        }
        int cnt = 0;
#pragma unroll
        for (int w = 0; w < NW1; w++) cnt += __popcll(~rem[w]);
        s_fb = (cnt < KPOST);
    }
    __syncthreads();

    // ---------- fallback: full 4096 NMS, boxes from GLOBAL (never taken) -----
    if (s_fb) {
        if (tid < NWORDS) remv[tid] = 0ull;
        __syncthreads();

        int colw = tid >> 4, sub = tid & 15;             // 16 lanes share colw
        for (int w = 0; w < NWORDS; w++) {
            if (tid < 64) {
                int i = w * 64 + tid;
                float4 A = g_box4[b][i]; float aA = g_area[b][i];
                unsigned long long d = 0ull;
#pragma unroll 1
                for (int j = tid + 1; j < 64; j++) {
                    int j2 = w * 64 + j;
                    if (iou_gt(A, aA, g_box4[b][j2], g_area[b][j2]))
                        d |= (1ull << j);
                }
                diag[tid] = d;
            }
            __syncthreads();
            if (tid == 0) {
                unsigned long long rem = remv[w], acc = 0ull;
#pragma unroll 1
                for (int bit = 0; bit < 64; bit++) {
                    if (!((rem >> bit) & 1ull)) { acc |= (1ull << bit); rem |= diag[bit]; }
                }
                acc_s[w] = acc;
            }
            __syncthreads();

            unsigned long long acc = acc_s[w];
            unsigned long long p = 0ull;
            if (colw > w) {
#pragma unroll 1
                for (int rr = 0; rr < 4; rr++) {
                    int rbit = sub + rr * 16;
                    if ((acc >> rbit) & 1ull) {
                        int i = w * 64 + rbit;
                        float4 A = g_box4[b][i]; float aA = g_area[b][i];
#pragma unroll 1
                        for (int j = 0; j < 64; j++) {
                            int j2 = colw * 64 + j;
                            if (iou_gt(A, aA, g_box4[b][j2], g_area[b][j2]))
                                p |= (1ull << j);
                        }
                    }
                }
            }
            part[colw * 17 + sub] = p;
            __syncthreads();
            if (tid < 64) {
                unsigned long long vv = remv[tid];
#pragma unroll 1
                for (int k = 0; k < 16; k++) vv |= part[tid * 17 + k];
                remv[tid] = vv;
            }
            __syncthreads();
        }
    }

    // ---------- parallel compact: one thread per box computes its rank -------
    for (int r = tid; r < KSEL; r += 1024) {
        int w = r >> 6, bit = r & 63;
        unsigned long long acc = acc_s[w];
        if ((acc >> bit) & 1ull) {
            int rank = 0;
            for (int k = 0; k < w; k++) rank += __popcll(acc_s[k]);
            rank += __popcll(acc & below_mask(bit));
            if (rank < KPOST) {
                const float* ro = &g_rois[b][r][0];
                int obase = (b * KPOST + rank) * 7;
#pragma unroll
                for (int c = 0; c < 7; c++) out[obase + c] = ro[c];
                out[SC_OFF + b * KPOST + rank] = g_scores[b][r];
                out[LB_OFF + b * KPOST + rank] = (float)(g_labels[b][r] + 1);
            }
        }
    }
}

// ---------------- launch (4 kernels) ----------------
extern "C" void kernel_launch(void* const* d_in, const int* in_sizes, int n_in,
                              void* d_out, int out_size) {
    const float* boxes = (const float*)d_in[0];
    const float* cls   = (const float*)d_in[1];
    if (n_in >= 2 && in_sizes[0] == BATCH * NPTS * NCLS) {
        boxes = (const float*)d_in[1];
        cls   = (const float*)d_in[0];
    }
    float* out = (float*)d_out;

    const int DSM_SEL  = 16384 + 16384 + CAND_CAP * 8;   // 81920 B
    const int DSM_SCAN = NCAP * 17 * 8;                  // 43520 B

    cudaFuncSetAttribute(k_select,
                         cudaFuncAttributeMaxDynamicSharedMemorySize, DSM_SEL);
    cudaFuncSetAttribute(k_scan_out,
                         cudaFuncAttributeMaxDynamicSharedMemorySize, DSM_SCAN);

    k_keys_hist<<<BATCH * NPTS / 256, 256>>>(cls, out);
    k_select<<<BATCH, 1024, DSM_SEL>>>(boxes, cls);
    k_mask0<<<dim3(NW1, NW1, BATCH), 64>>>();
    k_scan_out<<<BATCH, 1024, DSM_SCAN>>>(out);
}